// round 6
// baseline (speedup 1.0000x reference)
#include <cuda_runtime.h>
#include <cuda_bf16.h>
#include <math.h>

#define LOG8 2.0794415416798357f
#define MAXN 4096

// Packed per-point scratch (device globals: no allocation allowed)
__device__ float4 g_pt[MAXN];   // x, y, z, bits(block<<24 | c2<<16 | c1<<8 | c0)
__device__ int    g_w2[MAXN];   // batch<<16 | cy<<8 | cx

__device__ __forceinline__ float bucket_base(float d) {
    float x  = d * 2.0f;              // d / RES, exact
    float ax = fabsf(x);
    float r;
    if (ax <= 2.0f) {
        r = rintf(x);                 // jnp.round = half-to-even
    } else {
        float lr  = __fdiv_rn(logf(__fmul_rn(ax, 0.5f)), LOG8);
        float sup = fminf(rintf(__fsub_rn(2.0f, __fmul_rn(6.0f, lr))), 8.0f);
        r = (x > 0.0f) ? sup : -sup;
    }
    return 8.0f + r;
}

__global__ void pack_kernel(const float* __restrict__ xyz,
                            const int* __restrict__ grid, int N) {
    int i = blockIdx.x * blockDim.x + threadIdx.x;
    if (i >= N) return;
    float x = xyz[i * 3 + 0], y = xyz[i * 3 + 1], z = xyz[i * 3 + 2];
    int b  = grid[i * 5 + 0];
    int bl = grid[i * 5 + 1];
    int c0 = grid[i * 5 + 2];
    int c1 = grid[i * 5 + 3];
    int c2 = grid[i * 5 + 4];
    int cx = (int)ceilf(__fdiv_rn(x, 3.0f));   // SRF=3; xyz >= 0 so cx,cy in [0,4]
    int cy = (int)ceilf(__fdiv_rn(y, 3.0f));
    g_pt[i] = make_float4(x, y, z,
                          __int_as_float((bl << 24) | (c2 << 16) | (c1 << 8) | c0));
    g_w2[i] = (b << 16) | (cy << 8) | cx;
}

__global__ __launch_bounds__(256)
void pair_kernel(float* __restrict__ out, int N) {
    const int i  = blockIdx.y;
    const int j0 = (blockIdx.x * blockDim.x + threadIdx.x) * 4;
    if (j0 >= N) return;

    // ---- per-i data ----
    const float4 qi  = g_pt[i];
    const int    w1i = __float_as_int(qi.w);
    const int    w2i = g_w2[i];
    const int    bli = ((unsigned)w1i) >> 24;
    const int    sci = bli >> 1;

    // ---- 4 j points ----
    float4 qj[4];
    qj[0] = g_pt[j0 + 0]; qj[1] = g_pt[j0 + 1];
    qj[2] = g_pt[j0 + 2]; qj[3] = g_pt[j0 + 3];
    const int4 w2v = *reinterpret_cast<const int4*>(&g_w2[j0]);
    const int w2j[4] = {w2v.x, w2v.y, w2v.z, w2v.w};

    float dxv[12];
    float bkt[4], dsc[4], msk[4];

#pragma unroll
    for (int p = 0; p < 4; p++) {
        const float dx = qi.x - qj[p].x;
        const float dy = qi.y - qj[p].y;
        const float dz = qi.z - qj[p].z;
        const int w1j = __float_as_int(qj[p].w);
        const int blj = ((unsigned)w1j) >> 24;

        const unsigned d1 = __vabsdiffu4(w1i, w1j);   // [c0d, c1d, c2d, bld]
        const unsigned d2 = __vabsdiffu4(w2i, w2j[p]); // [cxd, cyd, bd, 0]

        bool m = ((d2 & 0x00FF0000u) == 0u) && (bli <= blj);   // batch_eq && block_le
        if (m) {
            const bool fk = (d1 & 0xFFFEFEFEu) == 0u;          // block_eq && coord_adj
            if (!fk) {
                const bool kc = (d2 & 0x0000FEFEu) == 0u;      // coarse xy adjacency
                const float r2 = __fadd_rn(__fadd_rn(__fmul_rn(dx, dx),
                                                     __fmul_rn(dy, dy)),
                                           __fmul_rn(dz, dz));
                m = kc && (r2 <= 9.0f);
            }
        }

        if (m) {
            dxv[p * 3 + 0] = dx;
            dxv[p * 3 + 1] = dy;
            dxv[p * 3 + 2] = dz;
            bkt[p] = __fadd_rn(__fadd_rn(__fmul_rn(289.0f, bucket_base(dx)),
                                         __fmul_rn(17.0f, bucket_base(dy))),
                               bucket_base(dz));
            dsc[p] = (float)((blj >> 1) - sci);
            msk[p] = 1.0f;
        } else {
            dxv[p * 3 + 0] = 0.0f; dxv[p * 3 + 1] = 0.0f; dxv[p * 3 + 2] = 0.0f;
            bkt[p] = 0.0f; dsc[p] = 0.0f; msk[p] = 0.0f;
        }
    }

    // ---- streaming stores (no reuse: evict-first) ----
    const size_t NN  = (size_t)N * (size_t)N;
    const size_t row = (size_t)i * N + (size_t)j0;

    float4* dx_out = reinterpret_cast<float4*>(out + row * 3);
    __stcs(dx_out + 0, make_float4(dxv[0], dxv[1], dxv[2],  dxv[3]));
    __stcs(dx_out + 1, make_float4(dxv[4], dxv[5], dxv[6],  dxv[7]));
    __stcs(dx_out + 2, make_float4(dxv[8], dxv[9], dxv[10], dxv[11]));

    __stcs(reinterpret_cast<float4*>(out + 3 * NN + row),
           make_float4(bkt[0], bkt[1], bkt[2], bkt[3]));
    __stcs(reinterpret_cast<float4*>(out + 4 * NN + row),
           make_float4(dsc[0], dsc[1], dsc[2], dsc[3]));
    __stcs(reinterpret_cast<float4*>(out + 5 * NN + row),
           make_float4(msk[0], msk[1], msk[2], msk[3]));
}

extern "C" void kernel_launch(void* const* d_in, const int* in_sizes, int n_in,
                              void* d_out, int out_size) {
    const float* xyz  = (const float*)d_in[0];   // [N,3] f32
    const int*   grid = (const int*)d_in[1];     // [N,5] i32
    float* out = (float*)d_out;

    const int N = in_sizes[0] / 3;               // 3072

    pack_kernel<<<(N + 255) / 256, 256>>>(xyz, grid, N);

    dim3 block(256, 1, 1);
    dim3 gridDim((N + 256 * 4 - 1) / (256 * 4), N, 1);
    pair_kernel<<<gridDim, block>>>(out, N);
}

// round 7
// speedup vs baseline: 1.1075x; 1.1075x over previous
#include <cuda_runtime.h>
#include <cuda_bf16.h>
#include <math.h>

#define LOG8 2.0794415416798357f
#define MAXN 4096
#define JTILE 1024   // j-elements per block (256 threads x 4)

// Packed per-point scratch (device globals: no allocation allowed)
__device__ float4 g_pt[MAXN];   // x, y, z, bits(block<<24 | c2<<16 | c1<<8 | c0)
__device__ int    g_w2[MAXN];   // batch<<16 | cy<<8 | cx

__device__ __forceinline__ float bucket_base(float d) {
    float x  = d * 2.0f;              // d / RES, exact
    float ax = fabsf(x);
    float r;
    if (ax <= 2.0f) {
        r = rintf(x);                 // jnp.round = half-to-even
    } else {
        float lr  = __fdiv_rn(logf(__fmul_rn(ax, 0.5f)), LOG8);
        float sup = fminf(rintf(__fsub_rn(2.0f, __fmul_rn(6.0f, lr))), 8.0f);
        r = (x > 0.0f) ? sup : -sup;
    }
    return 8.0f + r;
}

__global__ void pack_kernel(const float* __restrict__ xyz,
                            const int* __restrict__ grid, int N) {
    int i = blockIdx.x * blockDim.x + threadIdx.x;
    if (i >= N) return;
    float x = xyz[i * 3 + 0], y = xyz[i * 3 + 1], z = xyz[i * 3 + 2];
    int b  = grid[i * 5 + 0];
    int bl = grid[i * 5 + 1];
    int c0 = grid[i * 5 + 2];
    int c1 = grid[i * 5 + 3];
    int c2 = grid[i * 5 + 4];
    int cx = (int)ceilf(__fdiv_rn(x, 3.0f));
    int cy = (int)ceilf(__fdiv_rn(y, 3.0f));
    g_pt[i] = make_float4(x, y, z,
                          __int_as_float((bl << 24) | (c2 << 16) | (c1 << 8) | c0));
    g_w2[i] = (b << 16) | (cy << 8) | cx;
}

__device__ __forceinline__ unsigned smem_u32(const void* p) {
    return (unsigned)__cvta_generic_to_shared(p);
}

__global__ __launch_bounds__(256)
void pair_kernel(float* __restrict__ out, int N) {
    __shared__ float s_dxyz[JTILE * 3];   // 12 KB
    __shared__ float s_bkt[JTILE];        // 4 KB
    __shared__ float s_dsc[JTILE];        // 4 KB
    __shared__ float s_msk[JTILE];        // 4 KB

    const int i     = blockIdx.y;
    const int jbase = blockIdx.x * JTILE;
    const int t     = threadIdx.x;
    const int j0    = jbase + t * 4;

    // ---- per-i data ----
    const float4 qi  = g_pt[i];
    const int    w1i = __float_as_int(qi.w);
    const int    w2i = g_w2[i];
    const int    bli = ((unsigned)w1i) >> 24;
    const int    sci = bli >> 1;

    const int jcount = min(JTILE, N - jbase);   // multiple of 4 (N%4==0)

    if (t * 4 < jcount) {
        // ---- 4 j points ----
        float4 qj[4];
        qj[0] = g_pt[j0 + 0]; qj[1] = g_pt[j0 + 1];
        qj[2] = g_pt[j0 + 2]; qj[3] = g_pt[j0 + 3];
        const int4 w2v = *reinterpret_cast<const int4*>(&g_w2[j0]);
        const int w2j[4] = {w2v.x, w2v.y, w2v.z, w2v.w};

        float dxv[12];
        float bkt[4], dsc[4], msk[4];

#pragma unroll
        for (int p = 0; p < 4; p++) {
            const float dx = qi.x - qj[p].x;
            const float dy = qi.y - qj[p].y;
            const float dz = qi.z - qj[p].z;
            const int w1j = __float_as_int(qj[p].w);
            const int blj = ((unsigned)w1j) >> 24;

            const unsigned d1 = __vabsdiffu4(w1i, w1j);    // [c0d, c1d, c2d, bld]
            const unsigned d2 = __vabsdiffu4(w2i, w2j[p]); // [cxd, cyd, bd, 0]

            bool m = ((d2 & 0x00FF0000u) == 0u) && (bli <= blj);
            if (m) {
                const bool fk = (d1 & 0xFFFEFEFEu) == 0u;
                if (!fk) {
                    const bool kc = (d2 & 0x0000FEFEu) == 0u;
                    const float r2 = __fadd_rn(__fadd_rn(__fmul_rn(dx, dx),
                                                         __fmul_rn(dy, dy)),
                                               __fmul_rn(dz, dz));
                    m = kc && (r2 <= 9.0f);
                }
            }

            if (m) {
                dxv[p * 3 + 0] = dx;
                dxv[p * 3 + 1] = dy;
                dxv[p * 3 + 2] = dz;
                bkt[p] = __fadd_rn(__fadd_rn(__fmul_rn(289.0f, bucket_base(dx)),
                                             __fmul_rn(17.0f, bucket_base(dy))),
                                   bucket_base(dz));
                dsc[p] = (float)((blj >> 1) - sci);
                msk[p] = 1.0f;
            } else {
                dxv[p * 3 + 0] = 0.0f; dxv[p * 3 + 1] = 0.0f; dxv[p * 3 + 2] = 0.0f;
                bkt[p] = 0.0f; dsc[p] = 0.0f; msk[p] = 0.0f;
            }
        }

        // ---- stage to SMEM (layout == global layout of this block's slices) ----
        float4* sdx = reinterpret_cast<float4*>(&s_dxyz[t * 12]);
        sdx[0] = make_float4(dxv[0], dxv[1], dxv[2],  dxv[3]);
        sdx[1] = make_float4(dxv[4], dxv[5], dxv[6],  dxv[7]);
        sdx[2] = make_float4(dxv[8], dxv[9], dxv[10], dxv[11]);
        *reinterpret_cast<float4*>(&s_bkt[t * 4]) = make_float4(bkt[0], bkt[1], bkt[2], bkt[3]);
        *reinterpret_cast<float4*>(&s_dsc[t * 4]) = make_float4(dsc[0], dsc[1], dsc[2], dsc[3]);
        *reinterpret_cast<float4*>(&s_msk[t * 4]) = make_float4(msk[0], msk[1], msk[2], msk[3]);
    }

    __syncthreads();

    // ---- one thread drains the tile via 4 bulk async stores (bypasses L1) ----
    if (t == 0) {
        asm volatile("fence.proxy.async.shared::cta;" ::: "memory");

        const size_t NN  = (size_t)N * (size_t)N;
        const size_t row = (size_t)i * N + (size_t)jbase;

        float* g_dx = out + row * 3;
        float* g_bk = out + 3 * NN + row;
        float* g_ds = out + 4 * NN + row;
        float* g_mk = out + 5 * NN + row;

        const unsigned bytes1 = (unsigned)jcount * 4u;
        const unsigned bytes3 = bytes1 * 3u;

        asm volatile("cp.async.bulk.global.shared::cta.bulk_group [%0], [%1], %2;"
                     :: "l"(g_dx), "r"(smem_u32(s_dxyz)), "r"(bytes3) : "memory");
        asm volatile("cp.async.bulk.global.shared::cta.bulk_group [%0], [%1], %2;"
                     :: "l"(g_bk), "r"(smem_u32(s_bkt)), "r"(bytes1) : "memory");
        asm volatile("cp.async.bulk.global.shared::cta.bulk_group [%0], [%1], %2;"
                     :: "l"(g_ds), "r"(smem_u32(s_dsc)), "r"(bytes1) : "memory");
        asm volatile("cp.async.bulk.global.shared::cta.bulk_group [%0], [%1], %2;"
                     :: "l"(g_mk), "r"(smem_u32(s_msk)), "r"(bytes1) : "memory");
        asm volatile("cp.async.bulk.commit_group;" ::: "memory");
        asm volatile("cp.async.bulk.wait_group 0;" ::: "memory");
    }
}

extern "C" void kernel_launch(void* const* d_in, const int* in_sizes, int n_in,
                              void* d_out, int out_size) {
    const float* xyz  = (const float*)d_in[0];   // [N,3] f32
    const int*   grid = (const int*)d_in[1];     // [N,5] i32
    float* out = (float*)d_out;

    const int N = in_sizes[0] / 3;               // 3072

    pack_kernel<<<(N + 255) / 256, 256>>>(xyz, grid, N);

    dim3 block(256, 1, 1);
    dim3 gridDim((N + JTILE - 1) / JTILE, N, 1);
    pair_kernel<<<gridDim, block>>>(out, N);
}

// round 8
// speedup vs baseline: 1.1588x; 1.0463x over previous
#include <cuda_runtime.h>
#include <cuda_bf16.h>
#include <math.h>

#define LOG8 2.0794415416798357f
#define MAXN 4096
#define JTILE 1024   // j-elements per block (256 threads x 4)
#define ITERS 16     // i-rows per block

// Packed per-point scratch (device globals: no allocation allowed)
__device__ float4 g_pt[MAXN];   // x, y, z, bits(block<<24 | c2<<16 | c1<<8 | c0)
__device__ int    g_w2[MAXN];   // batch<<16 | cy<<8 | cx

__device__ __forceinline__ float bucket_base(float d) {
    float x  = d * 2.0f;              // d / RES, exact
    float ax = fabsf(x);
    float r;
    if (ax <= 2.0f) {
        r = rintf(x);                 // jnp.round = half-to-even
    } else {
        float lr  = __fdiv_rn(logf(__fmul_rn(ax, 0.5f)), LOG8);
        float sup = fminf(rintf(__fsub_rn(2.0f, __fmul_rn(6.0f, lr))), 8.0f);
        r = (x > 0.0f) ? sup : -sup;
    }
    return 8.0f + r;
}

__global__ void pack_kernel(const float* __restrict__ xyz,
                            const int* __restrict__ grid, int N) {
    int i = blockIdx.x * blockDim.x + threadIdx.x;
    if (i >= N) return;
    float x = xyz[i * 3 + 0], y = xyz[i * 3 + 1], z = xyz[i * 3 + 2];
    int b  = grid[i * 5 + 0];
    int bl = grid[i * 5 + 1];
    int c0 = grid[i * 5 + 2];
    int c1 = grid[i * 5 + 3];
    int c2 = grid[i * 5 + 4];
    int cx = (int)ceilf(__fdiv_rn(x, 3.0f));
    int cy = (int)ceilf(__fdiv_rn(y, 3.0f));
    g_pt[i] = make_float4(x, y, z,
                          __int_as_float((bl << 24) | (c2 << 16) | (c1 << 8) | c0));
    g_w2[i] = (b << 16) | (cy << 8) | cx;
}

__device__ __forceinline__ unsigned smem_u32(const void* p) {
    return (unsigned)__cvta_generic_to_shared(p);
}

// SMEM tile layout (floats): [dxyz: 3*JTILE][bkt: JTILE][dsc: JTILE][msk: JTILE]
#define TILE_F (6 * JTILE)

__global__ __launch_bounds__(256)
void pair_kernel(float* __restrict__ out, int N) {
    __shared__ float sbuf[2][TILE_F];   // 2 x 24 KB

    const int jbase = blockIdx.x * JTILE;
    const int i0    = blockIdx.y * ITERS;
    const int t     = threadIdx.x;
    const int j0    = jbase + t * 4;

    // ---- j-tile data: loaded ONCE, lives in registers for all 16 i-rows ----
    float4 qj[4];
    qj[0] = g_pt[j0 + 0]; qj[1] = g_pt[j0 + 1];
    qj[2] = g_pt[j0 + 2]; qj[3] = g_pt[j0 + 3];
    const int4 w2v = *reinterpret_cast<const int4*>(&g_w2[j0]);
    const int w2j[4] = {w2v.x, w2v.y, w2v.z, w2v.w};
    int w1j[4], blj[4];
#pragma unroll
    for (int p = 0; p < 4; p++) {
        w1j[p] = __float_as_int(qj[p].w);
        blj[p] = ((unsigned)w1j[p]) >> 24;
    }

    const size_t NN = (size_t)N * (size_t)N;

    for (int k = 0; k < ITERS; k++) {
        const int i     = i0 + k;
        const int phase = k & 1;
        float* sb = sbuf[phase];

        // ---- per-i data ----
        const float4 qi  = g_pt[i];
        const int    w1i = __float_as_int(qi.w);
        const int    w2i = g_w2[i];
        const int    bli = ((unsigned)w1i) >> 24;
        const int    sci = bli >> 1;

        float dxv[12];
        float bkt[4], dsc[4], msk[4];

#pragma unroll
        for (int p = 0; p < 4; p++) {
            const float dx = qi.x - qj[p].x;
            const float dy = qi.y - qj[p].y;
            const float dz = qi.z - qj[p].z;

            const unsigned d1 = __vabsdiffu4(w1i, w1j[p]);  // [c0d,c1d,c2d,bld]
            const unsigned d2 = __vabsdiffu4(w2i, w2j[p]);  // [cxd,cyd,bd,0]

            bool m = ((d2 & 0x00FF0000u) == 0u) && (bli <= blj[p]);
            if (m) {
                const bool fk = (d1 & 0xFFFEFEFEu) == 0u;
                if (!fk) {
                    const bool kc = (d2 & 0x0000FEFEu) == 0u;
                    const float r2 = __fadd_rn(__fadd_rn(__fmul_rn(dx, dx),
                                                         __fmul_rn(dy, dy)),
                                               __fmul_rn(dz, dz));
                    m = kc && (r2 <= 9.0f);
                }
            }

            if (m) {
                dxv[p * 3 + 0] = dx;
                dxv[p * 3 + 1] = dy;
                dxv[p * 3 + 2] = dz;
                bkt[p] = __fadd_rn(__fadd_rn(__fmul_rn(289.0f, bucket_base(dx)),
                                             __fmul_rn(17.0f, bucket_base(dy))),
                                   bucket_base(dz));
                dsc[p] = (float)((blj[p] >> 1) - sci);
                msk[p] = 1.0f;
            } else {
                dxv[p * 3 + 0] = 0.0f; dxv[p * 3 + 1] = 0.0f; dxv[p * 3 + 2] = 0.0f;
                bkt[p] = 0.0f; dsc[p] = 0.0f; msk[p] = 0.0f;
            }
        }

        // ---- make sure the TMA that read this buffer (iter k-2) is done ----
        if (t == 0 && k >= 2) {
            asm volatile("cp.async.bulk.wait_group 1;" ::: "memory");
        }
        __syncthreads();

        // ---- stage to SMEM (layout mirrors the global slices) ----
        float4* sdx = reinterpret_cast<float4*>(&sb[t * 12]);
        sdx[0] = make_float4(dxv[0], dxv[1], dxv[2],  dxv[3]);
        sdx[1] = make_float4(dxv[4], dxv[5], dxv[6],  dxv[7]);
        sdx[2] = make_float4(dxv[8], dxv[9], dxv[10], dxv[11]);
        *reinterpret_cast<float4*>(&sb[3 * JTILE + t * 4]) =
            make_float4(bkt[0], bkt[1], bkt[2], bkt[3]);
        *reinterpret_cast<float4*>(&sb[4 * JTILE + t * 4]) =
            make_float4(dsc[0], dsc[1], dsc[2], dsc[3]);
        *reinterpret_cast<float4*>(&sb[5 * JTILE + t * 4]) =
            make_float4(msk[0], msk[1], msk[2], msk[3]);

        __syncthreads();

        // ---- issue bulk async drain of this tile (overlaps next iteration) ----
        if (t == 0) {
            asm volatile("fence.proxy.async.shared::cta;" ::: "memory");

            const size_t row = (size_t)i * N + (size_t)jbase;
            float* g_dx = out + row * 3;
            float* g_bk = out + 3 * NN + row;
            float* g_ds = out + 4 * NN + row;
            float* g_mk = out + 5 * NN + row;

            const unsigned bytes1 = JTILE * 4u;
            const unsigned bytes3 = bytes1 * 3u;

            asm volatile("cp.async.bulk.global.shared::cta.bulk_group [%0], [%1], %2;"
                         :: "l"(g_dx), "r"(smem_u32(&sb[0])), "r"(bytes3) : "memory");
            asm volatile("cp.async.bulk.global.shared::cta.bulk_group [%0], [%1], %2;"
                         :: "l"(g_bk), "r"(smem_u32(&sb[3 * JTILE])), "r"(bytes1) : "memory");
            asm volatile("cp.async.bulk.global.shared::cta.bulk_group [%0], [%1], %2;"
                         :: "l"(g_ds), "r"(smem_u32(&sb[4 * JTILE])), "r"(bytes1) : "memory");
            asm volatile("cp.async.bulk.global.shared::cta.bulk_group [%0], [%1], %2;"
                         :: "l"(g_mk), "r"(smem_u32(&sb[5 * JTILE])), "r"(bytes1) : "memory");
            asm volatile("cp.async.bulk.commit_group;" ::: "memory");
        }
    }

    // ---- drain everything before the SMEM is deallocated (block exit) ----
    if (t == 0) {
        asm volatile("cp.async.bulk.wait_group 0;" ::: "memory");
    }
    __syncthreads();
}

extern "C" void kernel_launch(void* const* d_in, const int* in_sizes, int n_in,
                              void* d_out, int out_size) {
    const float* xyz  = (const float*)d_in[0];   // [N,3] f32
    const int*   grid = (const int*)d_in[1];     // [N,5] i32
    float* out = (float*)d_out;

    const int N = in_sizes[0] / 3;               // 3072 (divisible by JTILE and ITERS)

    pack_kernel<<<(N + 255) / 256, 256>>>(xyz, grid, N);

    dim3 block(256, 1, 1);
    dim3 gridDim(N / JTILE, N / ITERS, 1);
    pair_kernel<<<gridDim, block>>>(out, N);
}